// round 17
// baseline (speedup 1.0000x reference)
#include <cuda_runtime.h>
#include <cuda_fp16.h>
#include <stdint.h>

#define NB 8      // batch
#define TT 8      // time (slice t = TT/2)
#define V  512    // nodes
#define F  64     // features
#define KP 32     // feature pairs
#define BLK 64    // pair-block edge
#define HB  32    // half-block (i-split)
#define NBLK 8    // V/BLK
#define NHB 16    // V/HB
#define NPAIR 36  // NBLK*(NBLK+1)/2
#define NGRP (2 * NPAIR)  // 72 CTAs per n
#define TPB 128   // 4 warps; warp 32i x 16j; thread 4i x 4j

// colpartial[n][half-block slot][column j]; exactly one writer per entry.
__device__ float g_colpartial[NB][NHB][V];
// per-n barrier (72 arrivals each), reset by last finishing CTA -> replay-safe
__device__ int g_arrive[NB];
__device__ int g_flag[NB];
__device__ int g_done[NB];

__global__ __launch_bounds__(TPB, 4)
void fused_kernel(const float* __restrict__ x,
                  const float* __restrict__ a,
                  float* __restrict__ out) {
    __shared__ __half    yrow[HB + BLK][72];  // 96 rows fp16 staging (144B rows)
    __shared__ uint32_t  y2[KP][HB + BLK];    // feature-major half2: [k][v], v<32 i-side, v>=32 j-side
    __shared__ float     rpart[4][HB];        // per-warp row partials
    __shared__ __half2   sa2[KP];
    __shared__ float     sinv_q[BLK];         // 1/colsum for q cols (local 0..63)
    __shared__ float     sinv_p[HB];          // 1/colsum for this CTA's 32 p-cols

    const int n  = blockIdx.y;
    const int bx = blockIdx.x;                // 0..71
    int pairid = bx >> 1;
    const int h = bx & 1;                     // i half
    int p = 0, rem = pairid;
    while (rem > (NBLK - 1) - p) { rem -= NBLK - p; p++; }
    const int q = p + rem;

    const int tid  = threadIdx.x;
    const int lane = tid & 31, wid = tid >> 5;   // wid 0..3
    const int r    = lane >> 2, c = lane & 3;    // thread 4i x 4j
    const int wx   = wid;                        // warp j-quarter

    // ---- load i-half (32 rows) + j-block (64 rows) as fp16 ----
    const float4* xg = (const float4*)(x + ((size_t)n * TT + TT / 2) * V * F);
    for (int it = 0; it < 12; it++) {
        int idx = it * TPB + tid;               // 1536 float4 total
        int v = idx >> 4, ch = idx & 15;
        int src = (v < HB) ? (BLK * p + HB * h + v) : (BLK * q + (v - HB));
        float4 w = xg[(size_t)src * 16 + ch];
        *(__half2*)&yrow[v][ch * 4]     = __float22half2_rn(make_float2(w.x, w.y));
        *(__half2*)&yrow[v][ch * 4 + 2] = __float22half2_rn(make_float2(w.z, w.w));
    }
    if (tid < KP) sa2[tid] = __float22half2_rn(make_float2(a[2 * tid], a[2 * tid + 1]));
    __syncthreads();

    // ---- transpose to feature-major: 24 units of (4 fpairs x 32 v) ----
#pragma unroll
    for (int m = 0; m < 6; m++) {
        int u  = wid * 6 + m;                   // 0..23
        int kc = u & 7, vg = u >> 3;            // vg 0..2
        int v  = vg * 32 + lane;
        uint4 w = *(const uint4*)&yrow[v][kc * 8];
        y2[4 * kc + 0][v] = w.x;
        y2[4 * kc + 1][v] = w.y;
        y2[4 * kc + 2][v] = w.z;
        y2[4 * kc + 3][v] = w.w;
    }
    __syncthreads();

    const int is0 = 4 * r;                      // i offset in half-tile (0..28)
    const int js0 = 16 * wx + 4 * c;            // j offset in tile (0..60)
    const __half2 z = __float2half2_rn(0.0f);
    __half2 acc0[16], acc1[16];
#pragma unroll
    for (int pp = 0; pp < 16; pp++) { acc0[pp] = z; acc1[pp] = z; }

    // ---- main loop: fully unrolled k, static bank select, 1-deep prefetch ----
    uint4 iw = *(const uint4*)&y2[0][is0];
    uint4 jw = *(const uint4*)&y2[0][HB + js0];
#pragma unroll
    for (int k = 0; k < KP; k++) {
        uint4 iwn, jwn;
        if (k + 1 < KP) {
            iwn = *(const uint4*)&y2[k + 1][is0];
            jwn = *(const uint4*)&y2[k + 1][HB + js0];
        }
        const __half2 ak = sa2[k];
        __half2 ifr[4] = {*(__half2*)&iw.x, *(__half2*)&iw.y,
                          *(__half2*)&iw.z, *(__half2*)&iw.w};
        __half2 jfr[4] = {*(__half2*)&jw.x, *(__half2*)&jw.y,
                          *(__half2*)&jw.z, *(__half2*)&jw.w};
#pragma unroll
        for (int ii = 0; ii < 4; ii++)
#pragma unroll
            for (int jj = 0; jj < 4; jj++) {
                __half2 d = __habs2(__hsub2(ifr[ii], jfr[jj]));
                if (k < 16) acc0[ii * 4 + jj] = __hfma2(d, ak, acc0[ii * 4 + jj]);
                else        acc1[ii * 4 + jj] = __hfma2(d, ak, acc1[ii * 4 + jj]);
            }
        iw = iwn;
        jw = jwn;
    }

    // ---- tmpS (registers through the barrier) ----
    float t[16];
#pragma unroll
    for (int pp = 0; pp < 16; pp++) {
        float2 f = __half22float2(acc0[pp]);
        float2 g = __half22float2(acc1[pp]);
        float s  = (f.x + f.y) + (g.x + g.y);
        t[pp] = __expf(fmaxf(s, 0.0f));
    }

    // ---- column sums over the 32 i-rows -> slot [2p+h], q columns (direct) ----
    float cs[4];
#pragma unroll
    for (int jj = 0; jj < 4; jj++)
        cs[jj] = (t[0 * 4 + jj] + t[1 * 4 + jj]) + (t[2 * 4 + jj] + t[3 * 4 + jj]);
#pragma unroll
    for (int m = 4; m <= 16; m <<= 1)
#pragma unroll
        for (int jj = 0; jj < 4; jj++)
            cs[jj] += __shfl_xor_sync(0xFFFFFFFFu, cs[jj], m);
    if (r == 0) {
#pragma unroll
        for (int jj = 0; jj < 4; jj++)
            g_colpartial[n][2 * p + h][BLK * q + js0 + jj] = cs[jj];
    }

    // ---- row sums over all 64 j (per-warp 16, combined in smem) ----
    float rs[4];
#pragma unroll
    for (int ii = 0; ii < 4; ii++)
        rs[ii] = (t[ii * 4 + 0] + t[ii * 4 + 1]) + (t[ii * 4 + 2] + t[ii * 4 + 3]);
#pragma unroll
    for (int m = 1; m <= 2; m <<= 1)
#pragma unroll
        for (int ii = 0; ii < 4; ii++)
            rs[ii] += __shfl_xor_sync(0xFFFFFFFFu, rs[ii], m);
    if (c == 0)
#pragma unroll
        for (int ii = 0; ii < 4; ii++)
            rpart[wx][is0 + ii] = rs[ii];
    __syncthreads();

    if (p != q && tid < HB) {
        // full-q contribution to p-column (this half's 32 cols) -> slot [2q];
        // slot [2q+1] zeroed by the same (unique) writer.
        float v = (rpart[0][tid] + rpart[1][tid]) + (rpart[2][tid] + rpart[3][tid]);
        g_colpartial[n][2 * q]    [BLK * p + HB * h + tid] = v;
        g_colpartial[n][2 * q + 1][BLK * p + HB * h + tid] = 0.0f;
    }

    // ========== per-n barrier (72 CTAs): atomic arrive, load-only spin ==========
    __threadfence();
    __syncthreads();
    if (tid == 0) {
        int old = atomicAdd(&g_arrive[n], 1);
        if (old == NGRP - 1) {
            atomicExch(&g_flag[n], 1);
        } else {
            const int* fp = &g_flag[n];
            unsigned v;
            do {
                asm volatile("ld.acquire.gpu.global.u32 %0, [%1];"
                             : "=r"(v) : "l"(fp));
                if (!v) __nanosleep(64);
            } while (!v);
        }
    }
    __syncthreads();
    __threadfence();

    // ---- rebuild inverse column sums (16 half-block slots, L2-resident) ----
    if (tid < BLK) {
        float s = 0.0f;
#pragma unroll
        for (int b = 0; b < NHB; b++) s += g_colpartial[n][b][BLK * q + tid];
        sinv_q[tid] = 1.0f / s;
    } else if (tid < BLK + HB) {
        int jj = tid - BLK;
        float s = 0.0f;
#pragma unroll
        for (int b = 0; b < NHB; b++) s += g_colpartial[n][b][BLK * p + HB * h + jj];
        sinv_p[jj] = 1.0f / s;
    }
    __syncthreads();

    // ---- normalize + single write (direct half-tile + its transpose) ----
    float* on = out + (size_t)n * V * V;
    const int gi0 = BLK * p + HB * h + is0;
    const int gj0 = BLK * q + js0;
    const float4 invq = *(const float4*)&sinv_q[js0];
#pragma unroll
    for (int ii = 0; ii < 4; ii++) {
        float4 o = make_float4(t[ii * 4 + 0] * invq.x, t[ii * 4 + 1] * invq.y,
                               t[ii * 4 + 2] * invq.z, t[ii * 4 + 3] * invq.w);
        *(float4*)(on + (size_t)(gi0 + ii) * V + gj0) = o;
    }
    const float4 invp = *(const float4*)&sinv_p[is0];
#pragma unroll
    for (int jj = 0; jj < 4; jj++) {
        float4 o = make_float4(t[0 * 4 + jj] * invp.x, t[1 * 4 + jj] * invp.y,
                               t[2 * 4 + jj] * invp.z, t[3 * 4 + jj] * invp.w);
        *(float4*)(on + (size_t)(gj0 + jj) * V + gi0) = o;
    }

    // ---- per-n barrier reset by last finishing CTA ----
    __syncthreads();
    if (tid == 0) {
        int old = atomicAdd(&g_done[n], 1);
        if (old == NGRP - 1) {
            g_arrive[n] = 0;
            g_flag[n]   = 0;
            g_done[n]   = 0;
            __threadfence();
        }
    }
}

extern "C" void kernel_launch(void* const* d_in, const int* in_sizes, int n_in,
                              void* d_out, int out_size) {
    const float* x = (const float*)d_in[0];
    const float* a = (const float*)d_in[1];
    if (n_in >= 2 && in_sizes[0] == F && in_sizes[1] == NB * TT * V * F) {
        const float* t = x; x = a; a = t;
    }
    float* out = (float*)d_out;

    dim3 g1(NGRP, NB);    // 576 CTAs of 128 threads -> ~4 CTAs/SM phase overlap
    fused_kernel<<<g1, TPB>>>(x, a, out);
}